// round 2
// baseline (speedup 1.0000x reference)
#include <cuda_runtime.h>
#include <math.h>

// ---------------- problem constants ----------------
#define BATCH 4
#define D64   64
#define D32   32
#define D16   16
#define NTOK  (BATCH*4096)          // 16384 tokens
#define EDIM  16
#define KCODE 8192
#define N_MC  (BATCH*8*D64*D64*D64) // 8388608
#define OFF_MC     8388608
#define OFF_COMMIT 16777216
#define OFF_IDX    16777217

// ---------------- device scratch (static: no allocations) ----------------
__device__ float g_bufA[BATCH*32*D64*D64*D64];   // 33.5M floats
__device__ float g_bufB[BATCH*64*D32*D32*D32];   // 8.4M
__device__ float g_bufC[BATCH*128*D16*D16*D16];  // 2.1M
__device__ float g_bufD[BATCH*128*D16*D16*D16];  // 2.1M
__device__ float g_seq[NTOK*EDIM];
__device__ float g_q[BATCH*EDIM*4096];
__device__ float g_cnorm[KCODE];
__device__ float g_part[128];
__device__ int   g_idx[NTOK];
__device__ unsigned char g_zmask[NTOK];
__device__ int   g_flags;   // bit0: float32 evidence, bit1: uint8 evidence, none: int32

// ---------------- input dtype probe ----------------
__global__ void initflag_kernel() { g_flags = 0; }

// Scan the first 64MB (= guaranteed min size across uint8/int32/float32
// interpretations of 67108864 elements).
//  - any byte >= 2                    -> float32 data (exponent bytes)
//  - any 0x01 byte at offset%4 != 0   -> uint8 bools
//  - neither                          -> int32 bools (0/1 words)
__global__ void scan_kernel(const unsigned int* __restrict__ xw) {
    int base = blockIdx.x * 256 + threadIdx.x;    // 4096 blocks * 256 = 1M threads
    unsigned int f = 0, u = 0;
#pragma unroll
    for (int j = 0; j < 16; j++) {
        unsigned int w = xw[base + j * 1048576];
        f |= (w & 0xFEFEFEFEu);
        u |= (w & 0x01010100u);
    }
    int bits = (f ? 1 : 0) | (u ? 2 : 0);
    if (bits) atomicOr(&g_flags, bits);
}

// ---------------- bit pack: x (B,1,256,256,256) -> mc (B,8,64,64,64) ----------------
__global__ void pack_kernel(const unsigned char* __restrict__ xb, float* __restrict__ mc) {
    int i = blockIdx.x * 256 + threadIdx.x;
    if (i >= N_MC) return;
    int k  = i & 63;
    int j  = (i >> 6) & 63;
    int zi = (i >> 12) & 63;
    int c  = (i >> 18) & 7;
    int b  = i >> 21;
    int a   = c >> 1;
    int bb0 = (2 * c) & 3;
    int base = (((b * 256) + 4 * zi + a) * 256 + 4 * j + bb0) * 256 + 4 * k;
    int s = 0;
    int flags = g_flags;
    if (flags & 1) {                     // float32
        const float* xf = (const float*)xb;
        float4 f0 = *(const float4*)(xf + base);
        float4 f1 = *(const float4*)(xf + base + 256);
        if (f0.x != 0.f) s |= 1;   if (f0.y != 0.f) s |= 2;
        if (f0.z != 0.f) s |= 4;   if (f0.w != 0.f) s |= 8;
        if (f1.x != 0.f) s |= 16;  if (f1.y != 0.f) s |= 32;
        if (f1.z != 0.f) s |= 64;  if (f1.w != 0.f) s |= 128;
    } else if (flags & 2) {              // uint8
        unsigned int r0 = *(const unsigned int*)(xb + base);
        unsigned int r1 = *(const unsigned int*)(xb + base + 256);
#pragma unroll
        for (int cc = 0; cc < 4; cc++) {
            if ((r0 >> (8 * cc)) & 0xFF) s |= 1 << cc;
            if ((r1 >> (8 * cc)) & 0xFF) s |= 1 << (4 + cc);
        }
    } else {                             // int32
        const int* xi = (const int*)xb;
        int4 a0 = *(const int4*)(xi + base);
        int4 a1 = *(const int4*)(xi + base + 256);
        if (a0.x) s |= 1;   if (a0.y) s |= 2;
        if (a0.z) s |= 4;   if (a0.w) s |= 8;
        if (a1.x) s |= 16;  if (a1.y) s |= 32;
        if (a1.z) s |= 64;  if (a1.w) s |= 128;
    }
    mc[i] = (float)s * (1.0f / 255.0f);
}

// ---------------- zero-patch mask from mc ----------------
__global__ void zmask_kernel(const float* __restrict__ mc) {
    int i = blockIdx.x * 128 + threadIdx.x;
    if (i >= NTOK) return;
    int p = i & 4095, b = i >> 12;
    int zk = p & 15, zj = (p >> 4) & 15, zi = p >> 8;
    bool any = false;
    for (int c = 0; c < 8 && !any; c++)
        for (int dz = 0; dz < 4 && !any; dz++)
            for (int dy = 0; dy < 4 && !any; dy++) {
                const float4 v = *(const float4*)(mc + ((((b * 8 + c) * 64) + 4 * zi + dz) * 64 + 4 * zj + dy) * 64 + 4 * zk);
                if (v.x != 0.f || v.y != 0.f || v.z != 0.f || v.w != 0.f) any = true;
            }
    g_zmask[i] = any ? 0 : 1;
}

__device__ __forceinline__ float silu(float v) { return v / (1.f + expf(-v)); }

// ---------------- generic 3x3x3 conv (stride 1/2, pad 1), OCW channels x 4 x-positions/thread ----------------
template<int CIN, int OCW>
__launch_bounds__(128)
__global__ void conv_k3(const float* __restrict__ in, const float* __restrict__ wt,
                        const float* __restrict__ bias, float* __restrict__ out,
                        int Din, int Dout, int stride, int COUT, int act)
{
    extern __shared__ float sw[];   // [CIN*27][OCW]
    const int oc0 = blockIdx.y * OCW;
    const int b   = blockIdx.z;
#pragma unroll 1
    for (int o = 0; o < OCW; o++)
        for (int r = threadIdx.x; r < CIN * 27; r += 128)
            sw[r * OCW + o] = wt[(oc0 + o) * (CIN * 27) + r];
    __syncthreads();
    const int spatial = Dout * Dout * Dout;
    int gpos = (blockIdx.x * 128 + threadIdx.x) * 4;
    if (gpos >= spatial) return;
    int x0 = gpos % Dout; int t1 = gpos / Dout; int y = t1 % Dout; int z = t1 / Dout;

    float acc[OCW][4];
#pragma unroll
    for (int o = 0; o < OCW; o++) {
        float bv = bias[oc0 + o];
#pragma unroll
        for (int xx = 0; xx < 4; xx++) acc[o][xx] = bv;
    }
    const float* inb = in + b * CIN * Din * Din * Din;
    if (stride == 1) {
#pragma unroll 1
        for (int ic = 0; ic < CIN; ic++) {
            const float* inc = inb + ic * Din * Din * Din;
#pragma unroll 1
            for (int tz = 0; tz < 3; tz++) {
                int iz = z + tz - 1; if ((unsigned)iz >= (unsigned)Din) continue;
#pragma unroll
                for (int ty = 0; ty < 3; ty++) {
                    int iy = y + ty - 1; if ((unsigned)iy >= (unsigned)Din) continue;
                    const float* row = inc + (iz * Din + iy) * Din;
                    float r[6];
#pragma unroll
                    for (int jx = 0; jx < 6; jx++) {
                        int ix = x0 - 1 + jx;
                        r[jx] = ((unsigned)ix < (unsigned)Din) ? row[ix] : 0.f;
                    }
                    const float* swp = sw + (ic * 27 + tz * 9 + ty * 3) * OCW;
#pragma unroll
                    for (int tx = 0; tx < 3; tx++)
#pragma unroll
                        for (int o = 0; o < OCW; o++) {
                            float wv = swp[tx * OCW + o];
#pragma unroll
                            for (int xx = 0; xx < 4; xx++) acc[o][xx] += wv * r[xx + tx];
                        }
                }
            }
        }
    } else { // stride 2
#pragma unroll 1
        for (int ic = 0; ic < CIN; ic++) {
            const float* inc = inb + ic * Din * Din * Din;
#pragma unroll 1
            for (int tz = 0; tz < 3; tz++) {
                int iz = 2 * z + tz - 1; if ((unsigned)iz >= (unsigned)Din) continue;
#pragma unroll
                for (int ty = 0; ty < 3; ty++) {
                    int iy = 2 * y + ty - 1; if ((unsigned)iy >= (unsigned)Din) continue;
                    const float* row = inc + (iz * Din + iy) * Din;
                    float r[9];
#pragma unroll
                    for (int jx = 0; jx < 9; jx++) {
                        int ix = 2 * x0 - 1 + jx;
                        r[jx] = ((unsigned)ix < (unsigned)Din) ? row[ix] : 0.f;
                    }
                    const float* swp = sw + (ic * 27 + tz * 9 + ty * 3) * OCW;
#pragma unroll
                    for (int tx = 0; tx < 3; tx++)
#pragma unroll
                        for (int o = 0; o < OCW; o++) {
                            float wv = swp[tx * OCW + o];
#pragma unroll
                            for (int xx = 0; xx < 4; xx++) acc[o][xx] += wv * r[2 * xx + tx];
                        }
                }
            }
        }
    }
    int obase0 = (z * Dout + y) * Dout + x0;
#pragma unroll
    for (int o = 0; o < OCW; o++) {
        float* op = out + (b * COUT + oc0 + o) * spatial + obase0;
#pragma unroll
        for (int xx = 0; xx < 4; xx++) {
            float v = acc[o][xx];
            if (act) v = silu(v);
            op[xx] = v;
        }
    }
}

// ---------------- transposed conv: lhs_dilation=2, padding (2,1), kernel 3 ----------------
template<int CIN, int OCW>
__launch_bounds__(128)
__global__ void tconv_k3(const float* __restrict__ in, const float* __restrict__ wt,
                         const float* __restrict__ bias, float* __restrict__ out,
                         int Din, int COUT, int act)
{
    extern __shared__ float sw[];
    const int Dout = 2 * Din;
    const int oc0 = blockIdx.y * OCW;
    const int b   = blockIdx.z;
#pragma unroll 1
    for (int o = 0; o < OCW; o++)
        for (int r = threadIdx.x; r < CIN * 27; r += 128)
            sw[r * OCW + o] = wt[(oc0 + o) * (CIN * 27) + r];
    __syncthreads();
    const int spatial = Dout * Dout * Dout;
    int gpos = (blockIdx.x * 128 + threadIdx.x) * 4;
    if (gpos >= spatial) return;
    int x0 = gpos % Dout; int t1 = gpos / Dout; int y = t1 % Dout; int z = t1 / Dout;

    float acc[OCW][4];
#pragma unroll
    for (int o = 0; o < OCW; o++) {
        float bv = bias[oc0 + o];
#pragma unroll
        for (int xx = 0; xx < 4; xx++) acc[o][xx] = bv;
    }
    int izv[3], iyv[3]; bool vz[3], vy[3];
#pragma unroll
    for (int t = 0; t < 3; t++) {
        int pz = z + t - 2; vz[t] = (pz >= 0 && pz <= 2 * Din - 2 && !(pz & 1)); izv[t] = pz >> 1;
        int py = y + t - 2; vy[t] = (py >= 0 && py <= 2 * Din - 2 && !(py & 1)); iyv[t] = py >> 1;
    }
    const int ix0 = x0 >> 1;
    const float* inb = in + b * CIN * Din * Din * Din;
#pragma unroll 1
    for (int ic = 0; ic < CIN; ic++) {
        const float* inc = inb + ic * Din * Din * Din;
#pragma unroll 1
        for (int tz = 0; tz < 3; tz++) {
            if (!vz[tz]) continue;
#pragma unroll
            for (int ty = 0; ty < 3; ty++) {
                if (!vy[ty]) continue;
                const float* row = inc + (izv[tz] * Din + iyv[ty]) * Din;
                float r[3];
#pragma unroll
                for (int jx = 0; jx < 3; jx++) {
                    int ix = ix0 - 1 + jx;
                    r[jx] = ((unsigned)ix < (unsigned)Din) ? row[ix] : 0.f;
                }
                const float* swp = sw + (ic * 27 + tz * 9 + ty * 3) * OCW;
#pragma unroll
                for (int tx = 0; tx < 3; tx++)
#pragma unroll
                    for (int o = 0; o < OCW; o++) {
                        float wv = swp[tx * OCW + o];
#pragma unroll
                        for (int xx = 0; xx < 4; xx++) {
                            if (((xx + tx) & 1) == 0) {
                                int px = x0 + xx + tx - 2;
                                if (px >= 0) acc[o][xx] += wv * r[(xx + tx) >> 1];
                            }
                        }
                    }
            }
        }
    }
    int obase0 = (z * Dout + y) * Dout + x0;
#pragma unroll
    for (int o = 0; o < OCW; o++) {
        float* op = out + (b * COUT + oc0 + o) * spatial + obase0;
#pragma unroll
        for (int xx = 0; xx < 4; xx++) {
            float v = acc[o][xx];
            if (act) v = silu(v);
            op[xx] = v;
        }
    }
}

// ---------------- 1x1x1 convs ----------------
__global__ void quant_conv_kernel(const float* __restrict__ h, const float* __restrict__ w,
                                  const float* __restrict__ bias, float* __restrict__ seq)
{
    int i = blockIdx.x * 256 + threadIdx.x;          // B*4096*16, e fastest -> seq (B,N,E)
    if (i >= NTOK * EDIM) return;
    int e = i & 15; int p = (i >> 4) & 4095; int b = i >> 16;
    float acc = bias[e];
    const float* hp = h + (b * 128) * 4096 + p;
    const float* wp = w + e * 128;
#pragma unroll 8
    for (int ic = 0; ic < 128; ic++) acc += wp[ic] * hp[ic * 4096];
    seq[i] = acc;
}

__global__ void post_quant_kernel(const float* __restrict__ q, const float* __restrict__ w,
                                  const float* __restrict__ bias, float* __restrict__ out)
{
    int i = blockIdx.x * 256 + threadIdx.x;          // B*128*4096, p fastest
    if (i >= BATCH * 128 * 4096) return;
    int p = i & 4095; int oc = (i >> 12) & 127; int b = i >> 19;
    float acc = bias[oc];
    const float* qp = q + (b * EDIM) * 4096 + p;
    const float* wp = w + oc * EDIM;
#pragma unroll
    for (int e = 0; e < EDIM; e++) acc += wp[e] * qp[e * 4096];
    out[i] = acc;
}

// ---------------- VQ ----------------
__global__ void cnorm_kernel(const float* __restrict__ cb) {
    int k = blockIdx.x * 128 + threadIdx.x;
    if (k < KCODE) {
        float s = 0.f;
#pragma unroll
        for (int e = 0; e < EDIM; e++) { float c = cb[k * EDIM + e]; s += c * c; }
        g_cnorm[k] = s;
    }
}

__global__ void vq_kernel(const float* __restrict__ seq, const float* __restrict__ cb)
{
    __shared__ float stok[32 * 16];
    __shared__ float sc[128 * 16];
    __shared__ float sn[128];
    __shared__ float rd[128];
    __shared__ int   ri[128];
    const int tid = threadIdx.x;
    const int tok0 = blockIdx.x * 32;
    for (int i = tid; i < 512; i += 128) stok[i] = seq[tok0 * 16 + i];
    __syncthreads();
    const int t = tid & 31, g = tid >> 5;
    float s[16];
#pragma unroll
    for (int e = 0; e < 16; e++) s[e] = stok[t * 16 + e];
    float best = 3.4e38f; int bidx = 0;
    for (int tile = 0; tile < KCODE / 128; tile++) {
        __syncthreads();
        for (int i = tid; i < 2048; i += 128) sc[i] = cb[tile * 2048 + i];
        if (tid < 128) sn[tid] = g_cnorm[tile * 128 + tid];
        __syncthreads();
        for (int kk = g; kk < 128; kk += 4) {
            float dot = 0.f;
#pragma unroll
            for (int e = 0; e < 16; e++) dot += sc[kk * 16 + e] * s[e];
            float d = sn[kk] - 2.f * dot;
            if (d < best) { best = d; bidx = tile * 128 + kk; }
        }
    }
    rd[tid] = best; ri[tid] = bidx;
    __syncthreads();
    if (g == 0) {
        for (int gg = 1; gg < 4; gg++) {
            float d = rd[gg * 32 + t]; int k = ri[gg * 32 + t];
            if (d < best || (d == best && k < bidx)) { best = d; bidx = k; }
        }
        g_idx[tok0 + t] = bidx;
    }
}

// ---------------- commit loss (deterministic two-stage reduce) ----------------
__global__ void commit_kernel(const float* __restrict__ seq, const float* __restrict__ cb)
{
    __shared__ float sh[128];
    int t = blockIdx.x * 128 + threadIdx.x;
    float v = 0.f;
    if (!g_zmask[t]) {
        const float* s = seq + t * 16;
        const float* c = cb + g_idx[t] * 16;
        float a = 0.f;
#pragma unroll
        for (int e = 0; e < 16; e++) { float d = c[e] - s[e]; a += d * d; }
        v = a * (1.f / 16.f);
    }
    sh[threadIdx.x] = v; __syncthreads();
    for (int st = 64; st; st >>= 1) {
        if (threadIdx.x < st) sh[threadIdx.x] += sh[threadIdx.x + st];
        __syncthreads();
    }
    if (threadIdx.x == 0) g_part[blockIdx.x] = sh[0];
}

__global__ void commit_final(float* __restrict__ out) {
    if (threadIdx.x == 0) {
        float s = 0.f;
        for (int i = 0; i < 128; i++) s += g_part[i];
        out[0] = 0.25f * s / 16384.f;
    }
}

__global__ void fullidx_kernel(float* __restrict__ out) {
    int i = blockIdx.x * 256 + threadIdx.x;
    if (i < NTOK) out[i] = g_zmask[i] ? 0.f : (float)(g_idx[i] + 1);
}

__global__ void qbuild_kernel(const float* __restrict__ cb, const float* __restrict__ rep,
                              const float* __restrict__ pos)
{
    int i = blockIdx.x * 256 + threadIdx.x;          // B*16*4096, p fastest
    if (i >= BATCH * EDIM * 4096) return;
    int p = i & 4095; int e = (i >> 12) & 15; int b = i >> 16;
    int tok = (b << 12) + p;
    float v = g_zmask[tok] ? rep[e] : cb[g_idx[tok] * 16 + e];
    g_q[i] = v + pos[e * 4096 + p];
}

// ---------------- launch ----------------
extern "C" void kernel_launch(void* const* d_in, const int* in_sizes, int n_in,
                              void* d_out_, int out_size)
{
    const unsigned char* x = (const unsigned char*)d_in[0];
    const float* enc_in_w  = (const float*)d_in[1];
    const float* enc_in_b  = (const float*)d_in[2];
    const float* enc_d1_w  = (const float*)d_in[3];
    const float* enc_d1_b  = (const float*)d_in[4];
    const float* enc_d2_w  = (const float*)d_in[5];
    const float* enc_d2_b  = (const float*)d_in[6];
    const float* enc_out_w = (const float*)d_in[7];
    const float* enc_out_b = (const float*)d_in[8];
    const float* quant_w   = (const float*)d_in[9];
    const float* quant_b   = (const float*)d_in[10];
    const float* codebook  = (const float*)d_in[11];
    const float* rep_tok   = (const float*)d_in[12];
    const float* pos_emb   = (const float*)d_in[13];
    const float* pq_w      = (const float*)d_in[14];
    const float* pq_b      = (const float*)d_in[15];
    const float* dec_in_w  = (const float*)d_in[16];
    const float* dec_in_b  = (const float*)d_in[17];
    const float* dec_u1_w  = (const float*)d_in[18];
    const float* dec_u1_b  = (const float*)d_in[19];
    const float* dec_u2_w  = (const float*)d_in[20];
    const float* dec_u2_b  = (const float*)d_in[21];
    const float* dec_out_w = (const float*)d_in[22];
    const float* dec_out_b = (const float*)d_in[23];
    float* out = (float*)d_out_;

    float *pA, *pB, *pC, *pD, *pSeq, *pQ;
    cudaGetSymbolAddress((void**)&pA, g_bufA);
    cudaGetSymbolAddress((void**)&pB, g_bufB);
    cudaGetSymbolAddress((void**)&pC, g_bufC);
    cudaGetSymbolAddress((void**)&pD, g_bufD);
    cudaGetSymbolAddress((void**)&pSeq, g_seq);
    cudaGetSymbolAddress((void**)&pQ, g_q);
    cudaFuncSetAttribute(conv_k3<64, 8>,   cudaFuncAttributeMaxDynamicSharedMemorySize, 57344);
    cudaFuncSetAttribute(conv_k3<128, 4>,  cudaFuncAttributeMaxDynamicSharedMemorySize, 57344);
    cudaFuncSetAttribute(tconv_k3<128, 4>, cudaFuncAttributeMaxDynamicSharedMemorySize, 57344);
    cudaFuncSetAttribute(tconv_k3<64, 8>,  cudaFuncAttributeMaxDynamicSharedMemorySize, 57344);

    float* mc = out + OFF_MC;
    dim3 blk(128);

    initflag_kernel<<<1, 1>>>();
    scan_kernel<<<4096, 256>>>((const unsigned int*)x);
    pack_kernel<<<N_MC / 256, 256>>>(x, mc);
    zmask_kernel<<<NTOK / 128, 128>>>(mc);

    // encoder
    conv_k3<8, 16><<<dim3(512, 2, 4), blk, 8 * 27 * 16 * 4>>>(mc, enc_in_w, enc_in_b, pA, 64, 64, 1, 32, 1);
    conv_k3<32, 8><<<dim3(64, 8, 4), blk, 32 * 27 * 8 * 4>>>(pA, enc_d1_w, enc_d1_b, pB, 64, 32, 2, 64, 1);
    conv_k3<64, 8><<<dim3(8, 16, 4), blk, 64 * 27 * 8 * 4>>>(pB, enc_d2_w, enc_d2_b, pC, 32, 16, 2, 128, 1);
    conv_k3<128, 4><<<dim3(8, 32, 4), blk, 128 * 27 * 4 * 4>>>(pC, enc_out_w, enc_out_b, pD, 16, 16, 1, 128, 0);

    // quantization path
    cnorm_kernel<<<KCODE / 128, 128>>>(codebook);
    quant_conv_kernel<<<(NTOK * EDIM) / 256, 256>>>(pD, quant_w, quant_b, pSeq);
    vq_kernel<<<NTOK / 32, 128>>>(pSeq, codebook);
    commit_kernel<<<NTOK / 128, 128>>>(pSeq, codebook);
    commit_final<<<1, 1>>>(out + OFF_COMMIT);
    fullidx_kernel<<<NTOK / 256, 256>>>(out + OFF_IDX);
    qbuild_kernel<<<(BATCH * EDIM * 4096) / 256, 256>>>(codebook, rep_tok, pos_emb);
    post_quant_kernel<<<(BATCH * 128 * 4096) / 256, 256>>>(pQ, pq_w, pq_b, pC);

    // decoder
    conv_k3<128, 4><<<dim3(8, 32, 4), blk, 128 * 27 * 4 * 4>>>(pC, dec_in_w, dec_in_b, pD, 16, 16, 1, 128, 1);
    tconv_k3<128, 4><<<dim3(64, 16, 4), blk, 128 * 27 * 4 * 4>>>(pD, dec_u1_w, dec_u1_b, pB, 16, 64, 1);
    tconv_k3<64, 8><<<dim3(512, 4, 4), blk, 64 * 27 * 8 * 4>>>(pB, dec_u2_w, dec_u2_b, pA, 32, 32, 1);
    conv_k3<32, 8><<<dim3(512, 1, 4), blk, 32 * 27 * 8 * 4>>>(pA, dec_out_w, dec_out_b, out, 64, 64, 1, 8, 0);
}